// round 1
// baseline (speedup 1.0000x reference)
#include <cuda_runtime.h>

#define BB 2
#define CC 3
#define DD 128
#define HH 128
#define WW 128
#define NSEG 8
#define SEGL (HH / NSEG)            // 16 h-rows per warp task
#define NWARPS (BB * DD * NSEG)     // 2048 warp tasks
#define NTHREADS 128
#define NBLOCKS (NWARPS * 32 / NTHREADS)  // 512 blocks

// 13 partial sums:
// 0:mask 1:mx 2:my 3:mz 4:mae 5:mse 6:bg 7:gx 8:gy 9:gz 10:tx 11:ty 12:tz
__device__ double g_sums[13];

__global__ void zero_kernel() {
    if (threadIdx.x < 13) g_sums[threadIdx.x] = 0.0;
}

__device__ __forceinline__ float warp_sum(float v) {
#pragma unroll
    for (int o = 16; o; o >>= 1) v += __shfl_down_sync(0xffffffffu, v, o);
    return v;
}

__global__ __launch_bounds__(NTHREADS)
void loss_kernel(const float4* __restrict__ pred,
                 const float4* __restrict__ targ,
                 const float4* __restrict__ mask) {
    const int gwarp = (blockIdx.x * NTHREADS + threadIdx.x) >> 5;
    const int lane  = threadIdx.x & 31;

    // task decode: gwarp -> (b, d, seg)
    const int seg = gwarp & (NSEG - 1);
    const int bd  = gwarp >> 3;          // / NSEG
    const int d   = bd & (DD - 1);
    const int b   = bd >> 7;             // / DD
    const int h0  = seg * SEGL;

    const int   dcl = (d < DD - 1) ? d + 1 : d;       // clamped d+1
    const float dv  = (d < DD - 1) ? 1.0f : 0.0f;     // dx validity
    const float ze  = (lane < 31) ? 1.0f : 0.0f;      // w=127 edge

    const int  ROWQ = WW / 4;                         // 32 float4 per row
    const long CSTR = (long)DD * HH * ROWQ;           // channel stride (float4)

    long mo  = ((long)(b * DD + d)   * HH + h0) * ROWQ + lane;
    long mod = ((long)(b * DD + dcl) * HH + h0) * ROWQ + lane;
    long po  = ((long)((b * CC) * DD + d)   * HH + h0) * ROWQ + lane;
    long pod = ((long)((b * CC) * DD + dcl) * HH + h0) * ROWQ + lane;

    // previous-h state (diff = (p-t)*m, pin = p*m). Zero prev mask kills
    // the h0==0 boundary terms automatically (min(m,0)=0).
    float4 pm = make_float4(0.f, 0.f, 0.f, 0.f);
    float4 pdf[CC], ppi[CC];
#pragma unroll
    for (int c = 0; c < CC; c++) {
        pdf[c] = make_float4(0.f, 0.f, 0.f, 0.f);
        ppi[c] = make_float4(0.f, 0.f, 0.f, 0.f);
    }

    if (h0 > 0) {  // preload row h0-1 to seed the y-gradient
        pm = mask[mo - ROWQ];
#pragma unroll
        for (int c = 0; c < CC; c++) {
            float4 p = pred[po + c * CSTR - ROWQ];
            float4 t = targ[po + c * CSTR - ROWQ];
            pdf[c] = make_float4((p.x - t.x) * pm.x, (p.y - t.y) * pm.y,
                                 (p.z - t.z) * pm.z, (p.w - t.w) * pm.w);
            ppi[c] = make_float4(p.x * pm.x, p.y * pm.y, p.z * pm.z, p.w * pm.w);
        }
    }

    float s_m = 0.f, s_mx = 0.f, s_my = 0.f, s_mz = 0.f;
    float s_mae = 0.f, s_mse = 0.f, s_bg = 0.f;
    float s_gx = 0.f, s_gy = 0.f, s_gz = 0.f;
    float s_tx = 0.f, s_ty = 0.f, s_tz = 0.f;

    for (int hh = 0; hh < SEGL; hh++) {
        const float4 m  = mask[mo];
        const float4 md = mask[mod];

        const float4 mx4 = make_float4(fminf(m.x, md.x) * dv, fminf(m.y, md.y) * dv,
                                       fminf(m.z, md.z) * dv, fminf(m.w, md.w) * dv);
        const float4 my4 = make_float4(fminf(m.x, pm.x), fminf(m.y, pm.y),
                                       fminf(m.z, pm.z), fminf(m.w, pm.w));
        const float mnx = __shfl_down_sync(0xffffffffu, m.x, 1);
        const float mz0 = fminf(m.x, m.y), mz1 = fminf(m.y, m.z);
        const float mz2 = fminf(m.z, m.w), mz3 = fminf(m.w, mnx) * ze;

        s_m  += (m.x + m.y) + (m.z + m.w);
        s_mx += (mx4.x + mx4.y) + (mx4.z + mx4.w);
        s_my += (my4.x + my4.y) + (my4.z + my4.w);
        s_mz += (mz0 + mz1) + (mz2 + mz3);

#pragma unroll
        for (int c = 0; c < CC; c++) {
            const float4 p  = pred[po  + c * CSTR];
            const float4 t  = targ[po  + c * CSTR];
            const float4 pd = pred[pod + c * CSTR];
            const float4 td = targ[pod + c * CSTR];

            const float4 df = make_float4((p.x - t.x) * m.x, (p.y - t.y) * m.y,
                                          (p.z - t.z) * m.z, (p.w - t.w) * m.w);
            const float4 pi = make_float4(p.x * m.x, p.y * m.y, p.z * m.z, p.w * m.w);
            const float4 dfd = make_float4((pd.x - td.x) * md.x, (pd.y - td.y) * md.y,
                                           (pd.z - td.z) * md.z, (pd.w - td.w) * md.w);
            const float4 pid = make_float4(pd.x * md.x, pd.y * md.y,
                                           pd.z * md.z, pd.w * md.w);

            s_mae += (fabsf(df.x) + fabsf(df.y)) + (fabsf(df.z) + fabsf(df.w));
            s_mse += df.x * df.x + df.y * df.y + df.z * df.z + df.w * df.w;
            s_bg  += fabsf(p.x) * (1.f - m.x) + fabsf(p.y) * (1.f - m.y)
                   + fabsf(p.z) * (1.f - m.z) + fabsf(p.w) * (1.f - m.w);

            s_gx += fabsf(dfd.x - df.x) * mx4.x + fabsf(dfd.y - df.y) * mx4.y
                  + fabsf(dfd.z - df.z) * mx4.z + fabsf(dfd.w - df.w) * mx4.w;
            s_tx += fabsf(pid.x - pi.x) * mx4.x + fabsf(pid.y - pi.y) * mx4.y
                  + fabsf(pid.z - pi.z) * mx4.z + fabsf(pid.w - pi.w) * mx4.w;

            s_gy += fabsf(df.x - pdf[c].x) * my4.x + fabsf(df.y - pdf[c].y) * my4.y
                  + fabsf(df.z - pdf[c].z) * my4.z + fabsf(df.w - pdf[c].w) * my4.w;
            s_ty += fabsf(pi.x - ppi[c].x) * my4.x + fabsf(pi.y - ppi[c].y) * my4.y
                  + fabsf(pi.z - ppi[c].z) * my4.z + fabsf(pi.w - ppi[c].w) * my4.w;

            const float dnx = __shfl_down_sync(0xffffffffu, df.x, 1);
            const float pnx = __shfl_down_sync(0xffffffffu, pi.x, 1);
            s_gz += fabsf(df.y - df.x) * mz0 + fabsf(df.z - df.y) * mz1
                  + fabsf(df.w - df.z) * mz2 + fabsf(dnx - df.w) * mz3;
            s_tz += fabsf(pi.y - pi.x) * mz0 + fabsf(pi.z - pi.y) * mz1
                  + fabsf(pi.w - pi.z) * mz2 + fabsf(pnx - pi.w) * mz3;

            pdf[c] = df;
            ppi[c] = pi;
        }
        pm = m;
        mo += ROWQ; mod += ROWQ; po += ROWQ; pod += ROWQ;
    }

    float vals[13] = {s_m, s_mx, s_my, s_mz, s_mae, s_mse, s_bg,
                      s_gx, s_gy, s_gz, s_tx, s_ty, s_tz};
#pragma unroll
    for (int i = 0; i < 13; i++) {
        const float r = warp_sum(vals[i]);
        if (lane == 0) atomicAdd(&g_sums[i], (double)r);
    }
}

__global__ void finalize_kernel(float* __restrict__ out) {
    const double e = 1e-8;
    const double sm  = g_sums[0], smx = g_sums[1], smy = g_sums[2], smz = g_sums[3];
    const double mae = g_sums[4], mse = g_sums[5], bg = g_sums[6];
    const double gx  = g_sums[7], gy = g_sums[8], gz = g_sums[9];
    const double tx  = g_sums[10], ty = g_sums[11], tz = g_sums[12];
    const double inv = (double)BB * DD * HH * WW - sm;

    const double r = mae / (sm * 3.0 + e)
                   + 0.1   * (gx / (smx * 3.0 + e) + gy / (smy * 3.0 + e) + gz / (smz * 3.0 + e))
                   + 0.002 * (tx / (smx * 3.0 + e) + ty / (smy * 3.0 + e) + tz / (smz * 3.0 + e))
                   + 0.15  * (bg / (inv * 3.0 + e))
                   + mse / (sm * 3.0 + e);
    out[0] = (float)r;
}

extern "C" void kernel_launch(void* const* d_in, const int* in_sizes, int n_in,
                              void* d_out, int out_size) {
    // mask is the smallest input; pred/target keep their relative order
    int mi = 0;
    for (int i = 1; i < n_in; i++)
        if (in_sizes[i] < in_sizes[mi]) mi = i;
    int others[2], k = 0;
    for (int i = 0; i < 3; i++)
        if (i != mi) others[k++] = i;

    const float4* pred = (const float4*)d_in[others[0]];
    const float4* targ = (const float4*)d_in[others[1]];
    const float4* mask = (const float4*)d_in[mi];

    zero_kernel<<<1, 32>>>();
    loss_kernel<<<NBLOCKS, NTHREADS>>>(pred, targ, mask);
    finalize_kernel<<<1, 1>>>((float*)d_out);
}

// round 2
// speedup vs baseline: 1.4984x; 1.4984x over previous
#include <cuda_runtime.h>

#define BB 2
#define CC 3
#define DD 128
#define HH 128
#define WW 128
#define NSEG 16
#define SEGL (HH / NSEG)            // 8 h-rows per warp task
#define NWARPS (BB * DD * NSEG)     // 4096 warp tasks
#define NTHREADS 128
#define WPB (NTHREADS / 32)         // 4 warps/block
#define NBLOCKS (NWARPS / WPB)      // 1024 blocks

// 13 partial sums:
// 0:mask 1:mx 2:my 3:mz 4:mae 5:mse 6:bg 7:gx 8:gy 9:gz 10:tx 11:ty 12:tz
__device__ double g_sums[13];
__device__ unsigned int g_count;

__device__ __forceinline__ float warp_sum(float v) {
#pragma unroll
    for (int o = 16; o; o >>= 1) v += __shfl_down_sync(0xffffffffu, v, o);
    return v;
}

__global__ __launch_bounds__(NTHREADS)
void loss_kernel(const float4* __restrict__ pred,
                 const float4* __restrict__ targ,
                 const float4* __restrict__ mask,
                 float* __restrict__ out) {
    const int wid  = threadIdx.x >> 5;
    const int lane = threadIdx.x & 31;
    const int gwarp = blockIdx.x * WPB + wid;

    // task decode: gwarp -> (b, d, seg)
    const int seg = gwarp & (NSEG - 1);
    const int bd  = gwarp >> 4;          // / NSEG
    const int d   = bd & (DD - 1);
    const int b   = bd >> 7;             // / DD
    const int h0  = seg * SEGL;

    const int   dcl = (d < DD - 1) ? d + 1 : d;       // clamped d+1
    const float dv  = (d < DD - 1) ? 1.0f : 0.0f;     // dx validity
    const float ze  = (lane < 31) ? 1.0f : 0.0f;      // w=127 edge

    const int  ROWQ = WW / 4;                         // 32 float4 per row
    const long CSTR = (long)DD * HH * ROWQ;           // channel stride (float4)

    long mo  = ((long)(b * DD + d)   * HH + h0) * ROWQ + lane;
    long mod = ((long)(b * DD + dcl) * HH + h0) * ROWQ + lane;
    long po  = ((long)((b * CC) * DD + d)   * HH + h0) * ROWQ + lane;
    long pod = ((long)((b * CC) * DD + dcl) * HH + h0) * ROWQ + lane;

    // previous-h state (diff = (p-t)*m, pin = p*m). Zero prev mask kills
    // the h0==0 boundary terms automatically (min(m,0)=0).
    float4 pm = make_float4(0.f, 0.f, 0.f, 0.f);
    float4 pdf[CC], ppi[CC];
#pragma unroll
    for (int c = 0; c < CC; c++) {
        pdf[c] = make_float4(0.f, 0.f, 0.f, 0.f);
        ppi[c] = make_float4(0.f, 0.f, 0.f, 0.f);
    }

    if (h0 > 0) {  // preload row h0-1 to seed the y-gradient
        pm = mask[mo - ROWQ];
#pragma unroll
        for (int c = 0; c < CC; c++) {
            float4 p = pred[po + c * CSTR - ROWQ];
            float4 t = targ[po + c * CSTR - ROWQ];
            pdf[c] = make_float4((p.x - t.x) * pm.x, (p.y - t.y) * pm.y,
                                 (p.z - t.z) * pm.z, (p.w - t.w) * pm.w);
            ppi[c] = make_float4(p.x * pm.x, p.y * pm.y, p.z * pm.z, p.w * pm.w);
        }
    }

    float s_m = 0.f, s_mx = 0.f, s_my = 0.f, s_mz = 0.f;
    float s_mae = 0.f, s_mse = 0.f, s_bg = 0.f;
    float s_gx = 0.f, s_gy = 0.f, s_gz = 0.f;
    float s_tx = 0.f, s_ty = 0.f, s_tz = 0.f;

    for (int hh = 0; hh < SEGL; hh++) {
        const float4 m  = mask[mo];
        const float4 md = mask[mod];

        const float4 mx4 = make_float4(fminf(m.x, md.x) * dv, fminf(m.y, md.y) * dv,
                                       fminf(m.z, md.z) * dv, fminf(m.w, md.w) * dv);
        const float4 my4 = make_float4(fminf(m.x, pm.x), fminf(m.y, pm.y),
                                       fminf(m.z, pm.z), fminf(m.w, pm.w));
        const float mnx = __shfl_down_sync(0xffffffffu, m.x, 1);
        const float mz0 = fminf(m.x, m.y), mz1 = fminf(m.y, m.z);
        const float mz2 = fminf(m.z, m.w), mz3 = fminf(m.w, mnx) * ze;

        s_m  += (m.x + m.y) + (m.z + m.w);
        s_mx += (mx4.x + mx4.y) + (mx4.z + mx4.w);
        s_my += (my4.x + my4.y) + (my4.z + my4.w);
        s_mz += (mz0 + mz1) + (mz2 + mz3);

#pragma unroll
        for (int c = 0; c < CC; c++) {
            const float4 p  = pred[po  + c * CSTR];
            const float4 t  = targ[po  + c * CSTR];
            const float4 pd = pred[pod + c * CSTR];
            const float4 td = targ[pod + c * CSTR];

            const float4 df = make_float4((p.x - t.x) * m.x, (p.y - t.y) * m.y,
                                          (p.z - t.z) * m.z, (p.w - t.w) * m.w);
            const float4 pi = make_float4(p.x * m.x, p.y * m.y, p.z * m.z, p.w * m.w);
            const float4 dfd = make_float4((pd.x - td.x) * md.x, (pd.y - td.y) * md.y,
                                           (pd.z - td.z) * md.z, (pd.w - td.w) * md.w);
            const float4 pid = make_float4(pd.x * md.x, pd.y * md.y,
                                           pd.z * md.z, pd.w * md.w);

            s_mae += (fabsf(df.x) + fabsf(df.y)) + (fabsf(df.z) + fabsf(df.w));
            s_mse += df.x * df.x + df.y * df.y + df.z * df.z + df.w * df.w;
            s_bg  += fabsf(p.x) * (1.f - m.x) + fabsf(p.y) * (1.f - m.y)
                   + fabsf(p.z) * (1.f - m.z) + fabsf(p.w) * (1.f - m.w);

            s_gx += fabsf(dfd.x - df.x) * mx4.x + fabsf(dfd.y - df.y) * mx4.y
                  + fabsf(dfd.z - df.z) * mx4.z + fabsf(dfd.w - df.w) * mx4.w;
            s_tx += fabsf(pid.x - pi.x) * mx4.x + fabsf(pid.y - pi.y) * mx4.y
                  + fabsf(pid.z - pi.z) * mx4.z + fabsf(pid.w - pi.w) * mx4.w;

            s_gy += fabsf(df.x - pdf[c].x) * my4.x + fabsf(df.y - pdf[c].y) * my4.y
                  + fabsf(df.z - pdf[c].z) * my4.z + fabsf(df.w - pdf[c].w) * my4.w;
            s_ty += fabsf(pi.x - ppi[c].x) * my4.x + fabsf(pi.y - ppi[c].y) * my4.y
                  + fabsf(pi.z - ppi[c].z) * my4.z + fabsf(pi.w - ppi[c].w) * my4.w;

            const float dnx = __shfl_down_sync(0xffffffffu, df.x, 1);
            const float pnx = __shfl_down_sync(0xffffffffu, pi.x, 1);
            s_gz += fabsf(df.y - df.x) * mz0 + fabsf(df.z - df.y) * mz1
                  + fabsf(df.w - df.z) * mz2 + fabsf(dnx - df.w) * mz3;
            s_tz += fabsf(pi.y - pi.x) * mz0 + fabsf(pi.z - pi.y) * mz1
                  + fabsf(pi.w - pi.z) * mz2 + fabsf(pnx - pi.w) * mz3;

            pdf[c] = df;
            ppi[c] = pi;
        }
        pm = m;
        mo += ROWQ; mod += ROWQ; po += ROWQ; pod += ROWQ;
    }

    // ---- block-level reduction: warp -> smem -> 13 atomics per block ----
    __shared__ float red[WPB][13];
    float vals[13] = {s_m, s_mx, s_my, s_mz, s_mae, s_mse, s_bg,
                      s_gx, s_gy, s_gz, s_tx, s_ty, s_tz};
#pragma unroll
    for (int i = 0; i < 13; i++) {
        const float r = warp_sum(vals[i]);
        if (lane == 0) red[wid][i] = r;
    }
    __syncthreads();

    if (threadIdx.x < 13) {
        float acc = red[0][threadIdx.x];
#pragma unroll
        for (int w = 1; w < WPB; w++) acc += red[w][threadIdx.x];
        atomicAdd(&g_sums[threadIdx.x], (double)acc);
        __threadfence();
    }
    __syncthreads();

    // ---- last block finalizes + resets scratch (graph-replay determinism) ----
    if (threadIdx.x == 0) {
        const unsigned int old = atomicAdd(&g_count, 1u);
        if (old == NBLOCKS - 1) {
            double s[13];
#pragma unroll
            for (int i = 0; i < 13; i++) s[i] = atomicAdd(&g_sums[i], 0.0);
            const double e = 1e-8;
            const double sm  = s[0], smx = s[1], smy = s[2], smz = s[3];
            const double mae = s[4], mse = s[5], bg = s[6];
            const double gx  = s[7], gy = s[8], gz = s[9];
            const double tx  = s[10], ty = s[11], tz = s[12];
            const double inv = (double)BB * DD * HH * WW - sm;

            const double r = mae / (sm * 3.0 + e)
                           + 0.1   * (gx / (smx * 3.0 + e) + gy / (smy * 3.0 + e) + gz / (smz * 3.0 + e))
                           + 0.002 * (tx / (smx * 3.0 + e) + ty / (smy * 3.0 + e) + tz / (smz * 3.0 + e))
                           + 0.15  * (bg / (inv * 3.0 + e))
                           + mse / (sm * 3.0 + e);
            out[0] = (float)r;

#pragma unroll
            for (int i = 0; i < 13; i++) g_sums[i] = 0.0;
            g_count = 0u;
        }
    }
}

extern "C" void kernel_launch(void* const* d_in, const int* in_sizes, int n_in,
                              void* d_out, int out_size) {
    // mask is the smallest input; pred/target keep their relative order
    int mi = 0;
    for (int i = 1; i < n_in; i++)
        if (in_sizes[i] < in_sizes[mi]) mi = i;
    int others[2], k = 0;
    for (int i = 0; i < 3; i++)
        if (i != mi) others[k++] = i;

    const float4* pred = (const float4*)d_in[others[0]];
    const float4* targ = (const float4*)d_in[others[1]];
    const float4* mask = (const float4*)d_in[mi];

    loss_kernel<<<NBLOCKS, NTHREADS>>>(pred, targ, mask, (float*)d_out);
}